// round 1
// baseline (speedup 1.0000x reference)
#include <cuda_runtime.h>
#include <cstddef>

// Problem constants
#define LCH   4096          // chain length
#define BATCH 4096          // batch rows
#define SEG   32            // segment size
#define NSEG  (LCH / SEG)   // 128 segments per row

// Scratch: __device__ globals (allocation-free rule)
__device__ float    g_P[(size_t)BATCH * NSEG * 4];   // fwd transfer matrices [b][s][4]  (8 MB)
__device__ float    g_Q[(size_t)BATCH * NSEG * 4];   // bwd transfer matrices [b][s][4]  (8 MB)
__device__ float    g_F[(size_t)BATCH * NSEG * 2];   // fwd boundary msgs     [b][s][2]  (4 MB)
__device__ float    g_G[(size_t)BATCH * NSEG * 2];   // bwd boundary msgs     [b][s][2]  (4 MB)
__device__ unsigned g_bits[(size_t)BATCH * NSEG];    // packed obs bits       [b][s]     (2 MB)

// Shared potential computation: psi diag/offdiag, phi per (obs, state)
struct Pots {
    float pd, po;          // psi[k==l], psi[k!=l]
    float pA0, pA1;        // phi(obs=0, state=0/1)
    float pB0, pB1;        // phi(obs=1, state=0/1)
};

__device__ __forceinline__ Pots make_pots(const float* jp, const float* bp) {
    Pots P;
    float j  = jp[0];
    float b0 = bp[0];
    float b1 = bp[1];
    P.pd  = expf( 0.25f * j);   // values[k]*values[l] = +0.25 (k==l)
    P.po  = expf(-0.25f * j);   // -0.25 (k!=l)
    P.pA0 = expf(-0.5f * b0);   // phi(o=0, s=0): b[0]*(-0.5)
    P.pA1 = expf( 0.5f * b0);
    P.pB0 = expf(-0.5f * b1);
    P.pB1 = expf( 0.5f * b1);
    return P;
}

// ---------------------------------------------------------------------------
// Phase 1: per (row, segment) build P_s (forward transfer, left-composed),
// Q_s (backward transfer, right-composed), and pack obs bits.
// ---------------------------------------------------------------------------
__global__ void __launch_bounds__(NSEG)
phase1(const float* __restrict__ jp, const float* __restrict__ bp,
       const int* __restrict__ obs)
{
    const int s = threadIdx.x;    // segment 0..127
    const int b = blockIdx.x;     // row 0..4095
    const Pots pt = make_pots(jp, bp);

    // Load 32 obs ints (8 x int4), pack LSBs into a 32-bit mask.
    const int4* op = reinterpret_cast<const int4*>(obs + (size_t)b * LCH + (size_t)s * SEG);
    unsigned bits = 0u;
#pragma unroll
    for (int q = 0; q < 8; q++) {
        int4 v = op[q];
        bits |= (unsigned)(v.x & 1) << (4 * q + 0);
        bits |= (unsigned)(v.y & 1) << (4 * q + 1);
        bits |= (unsigned)(v.z & 1) << (4 * q + 2);
        bits |= (unsigned)(v.w & 1) << (4 * q + 3);
    }

    // (max,*) identity
    float P00 = 1.f, P01 = 0.f, P10 = 0.f, P11 = 1.f;
    float Q00 = 1.f, Q01 = 0.f, Q10 = 0.f, Q11 = 1.f;

#pragma unroll
    for (int i = 0; i < SEG; i++) {
        const int   o  = (bits >> i) & 1;
        const float f0 = o ? pt.pB0 : pt.pA0;
        const float f1 = o ? pt.pB1 : pt.pA1;

        // P <- A_t (x) P      (A[k][l] = psi[k,l]*phi[l])
        {
            float x0 = f0 * P00, x1 = f1 * P10;   // column 0
            float y0 = f0 * P01, y1 = f1 * P11;   // column 1
            P00 = fmaxf(x0 * pt.pd, x1 * pt.po);
            P10 = fmaxf(x0 * pt.po, x1 * pt.pd);
            P01 = fmaxf(y0 * pt.pd, y1 * pt.po);
            P11 = fmaxf(y0 * pt.po, y1 * pt.pd);
        }
        // Q <- Q (x) A_t :  (Q A)[k][c] = phi[c] * max(Q[k][0]*psi[0,c], Q[k][1]*psi[1,c])
        {
            float q00 = f0 * fmaxf(Q00 * pt.pd, Q01 * pt.po);
            float q01 = f1 * fmaxf(Q00 * pt.po, Q01 * pt.pd);
            float q10 = f0 * fmaxf(Q10 * pt.pd, Q11 * pt.po);
            float q11 = f1 * fmaxf(Q10 * pt.po, Q11 * pt.pd);
            Q00 = q00; Q01 = q01; Q10 = q10; Q11 = q11;
        }
    }

    const size_t idx = (size_t)b * NSEG + s;
    reinterpret_cast<float4*>(g_P)[idx] = make_float4(P00, P01, P10, P11);
    reinterpret_cast<float4*>(g_Q)[idx] = make_float4(Q00, Q01, Q10, Q11);
    g_bits[idx] = bits;
}

// ---------------------------------------------------------------------------
// Phase 2: per-row sequential scans over segments.
//   tid <  BATCH : forward boundary msgs  F[b][s] = f at t = s*SEG   (F[0]=1)
//   tid >= BATCH : backward boundary msgs G[b][s] = b at t = (s+1)*SEG-1 (G[K-1]=1)
// ---------------------------------------------------------------------------
__global__ void __launch_bounds__(128)
phase2()
{
    const int tid = blockIdx.x * blockDim.x + threadIdx.x;
    if (tid < BATCH) {
        const int b = tid;
        const float4* P = reinterpret_cast<const float4*>(g_P) + (size_t)b * NSEG;
        float2*       F = reinterpret_cast<float2*>(g_F) + (size_t)b * NSEG;
        float f0 = 1.f, f1 = 1.f;
        for (int s = 0; s < NSEG; s++) {
            F[s] = make_float2(f0, f1);
            float4 p = P[s];
            float n0 = fmaxf(p.x * f0, p.y * f1);
            float n1 = fmaxf(p.z * f0, p.w * f1);
            f0 = n0; f1 = n1;
        }
    } else if (tid < 2 * BATCH) {
        const int b = tid - BATCH;
        const float4* Q = reinterpret_cast<const float4*>(g_Q) + (size_t)b * NSEG;
        float2*       G = reinterpret_cast<float2*>(g_G) + (size_t)b * NSEG;
        float g0 = 1.f, g1 = 1.f;
        for (int s = NSEG - 1; s >= 0; s--) {
            G[s] = make_float2(g0, g1);
            float4 q = Q[s];
            float n0 = fmaxf(q.x * g0, q.y * g1);
            float n1 = fmaxf(q.z * g0, q.w * g1);
            g0 = n0; g1 = n1;
        }
    }
}

// ---------------------------------------------------------------------------
// Phase 3: per (row, segment) — rebuild backward msgs in registers (right to
// left), then forward sweep producing beliefs, vectorized float4 stores.
// ---------------------------------------------------------------------------
__global__ void __launch_bounds__(NSEG)
phase3(const float* __restrict__ jp, const float* __restrict__ bp,
       float* __restrict__ out)
{
    const int s = threadIdx.x;
    const int b = blockIdx.x;
    const Pots pt = make_pots(jp, bp);

    const size_t idx  = (size_t)b * NSEG + s;
    const unsigned bits = g_bits[idx];
    const float2 F2 = reinterpret_cast<const float2*>(g_F)[idx];
    const float2 G2 = reinterpret_cast<const float2*>(g_G)[idx];

    // Backward messages within segment: b_i = A_{i+1} (x) b_{i+1}, b_{S-1} = G_s.
    float bk0[SEG], bk1[SEG];
    bk0[SEG - 1] = G2.x;
    bk1[SEG - 1] = G2.y;
#pragma unroll
    for (int i = SEG - 2; i >= 0; i--) {
        const int   o  = (bits >> (i + 1)) & 1;
        const float f0 = o ? pt.pB0 : pt.pA0;
        const float f1 = o ? pt.pB1 : pt.pA1;
        float x0 = f0 * bk0[i + 1];
        float x1 = f1 * bk1[i + 1];
        bk0[i] = fmaxf(x0 * pt.pd, x1 * pt.po);
        bk1[i] = fmaxf(x0 * pt.po, x1 * pt.pd);
    }

    // Forward sweep + beliefs.  out[b][k][t], t = s*SEG + i
    float f0 = F2.x, f1 = F2.y;
    float* out0 = out + (size_t)b * 2 * LCH + (size_t)s * SEG;   // k = 0
    float* out1 = out0 + LCH;                                     // k = 1
    float buf0[4], buf1[4];
#pragma unroll
    for (int i = 0; i < SEG; i++) {
        const int   o  = (bits >> i) & 1;
        const float p0 = o ? pt.pB0 : pt.pA0;
        const float p1 = o ? pt.pB1 : pt.pA1;
        const float x0 = p0 * f0;
        const float x1 = p1 * f1;
        buf0[i & 3] = x0 * bk0[i];
        buf1[i & 3] = x1 * bk1[i];
        if ((i & 3) == 3) {
            *reinterpret_cast<float4*>(out0 + i - 3) = make_float4(buf0[0], buf0[1], buf0[2], buf0[3]);
            *reinterpret_cast<float4*>(out1 + i - 3) = make_float4(buf1[0], buf1[1], buf1[2], buf1[3]);
        }
        f0 = fmaxf(x0 * pt.pd, x1 * pt.po);
        f1 = fmaxf(x0 * pt.po, x1 * pt.pd);
    }
}

// ---------------------------------------------------------------------------
extern "C" void kernel_launch(void* const* d_in, const int* in_sizes, int n_in,
                              void* d_out, int out_size)
{
    // Defensive input identification by element count: j(1), b(2), obs(B*L).
    const float* jp  = nullptr;
    const float* bp  = nullptr;
    const int*   obs = nullptr;
    for (int i = 0; i < n_in; i++) {
        if (in_sizes[i] == 1)                 jp  = (const float*)d_in[i];
        else if (in_sizes[i] == 2)            bp  = (const float*)d_in[i];
        else                                   obs = (const int*)d_in[i];
    }
    float* out = (float*)d_out;

    phase1<<<BATCH, NSEG>>>(jp, bp, obs);
    phase2<<<(2 * BATCH + 127) / 128, 128>>>();
    phase3<<<BATCH, NSEG>>>(jp, bp, out);
}

// round 2
// speedup vs baseline: 1.3572x; 1.3572x over previous
#include <cuda_runtime.h>
#include <cstddef>

#define LCH   4096
#define BATCH 4096
#define SEG   32
#define NSEG  128          // segments per row

// Scratch (__device__ globals: allocation-free rule)
__device__ float    g_P[(size_t)BATCH * NSEG * 4];   // fwd transfer matrices [b][s][4]
__device__ float    g_Q[(size_t)BATCH * NSEG * 4];   // bwd transfer matrices [b][s][4]
__device__ float    g_F[(size_t)BATCH * NSEG * 2];   // fwd boundary msgs
__device__ float    g_G[(size_t)BATCH * NSEG * 2];   // bwd boundary msgs
__device__ unsigned g_bits[(size_t)BATCH * NSEG];    // packed obs bits

struct Pots { float pd, po, pA0, pA1, pB0, pB1; };

__device__ __forceinline__ Pots make_pots(const float* jp, const float* bp) {
    Pots P;
    float j = jp[0], b0 = bp[0], b1 = bp[1];
    P.pd  = expf( 0.25f * j);
    P.po  = expf(-0.25f * j);
    P.pA0 = expf(-0.5f * b0);  P.pA1 = expf(0.5f * b0);
    P.pB0 = expf(-0.5f * b1);  P.pB1 = expf(0.5f * b1);
    return P;
}

// ---------------------------------------------------------------------------
// Phase 1: one block per row. Coalesced obs reads + ballot bit-pack, 4-bit
// LUT of 4-step transfer matrices, coalesced P/Q/bits stores.
// ---------------------------------------------------------------------------
__global__ void __launch_bounds__(128)
phase1(const float* __restrict__ jp, const float* __restrict__ bp,
       const int* __restrict__ obs)
{
    const int t = threadIdx.x, b = blockIdx.x;
    const int lane = t & 31, warp = t >> 5;

    __shared__ unsigned smBits[NSEG];
    __shared__ float4   lutP[16], lutQ[16];

    const Pots pt = make_pots(jp, bp);

    // Coalesced obs reads; ballot assembles one segment mask per (warp, iter).
    // Iter q, warp w covers positions [q*128 + w*32, +32) = segment q*4 + w.
    const int* row = obs + (size_t)b * LCH;
    unsigned mybits = 0u;
#pragma unroll
    for (int q = 0; q < 32; q++) {
        int v = row[q * 128 + t];
        unsigned bal = __ballot_sync(0xffffffffu, v & 1);
        if (lane == q) mybits = bal;   // lane q keeps segment q*4+warp
    }
    smBits[lane * 4 + warp] = mybits;

    // Build 4-bit LUTs: chunkP(m) = A3∘A2∘A1∘A0, chunkQ(m) = A0·A1·A2·A3
    if (t < 16) {
        float p00 = 1.f, p01 = 0.f, p10 = 0.f, p11 = 1.f;
        float q00 = 1.f, q01 = 0.f, q10 = 0.f, q11 = 1.f;
#pragma unroll
        for (int i = 0; i < 4; i++) {
            int   o  = (t >> i) & 1;
            float f0 = o ? pt.pB0 : pt.pA0;
            float f1 = o ? pt.pB1 : pt.pA1;
            // P <- A_i (x) P
            float x0 = f0 * p00, x1 = f1 * p10, y0 = f0 * p01, y1 = f1 * p11;
            p00 = fmaxf(x0 * pt.pd, x1 * pt.po); p10 = fmaxf(x0 * pt.po, x1 * pt.pd);
            p01 = fmaxf(y0 * pt.pd, y1 * pt.po); p11 = fmaxf(y0 * pt.po, y1 * pt.pd);
            // Q <- Q . A_i
            float a = f0 * fmaxf(q00 * pt.pd, q01 * pt.po);
            float c = f1 * fmaxf(q00 * pt.po, q01 * pt.pd);
            float d = f0 * fmaxf(q10 * pt.pd, q11 * pt.po);
            float e = f1 * fmaxf(q10 * pt.po, q11 * pt.pd);
            q00 = a; q01 = c; q10 = d; q11 = e;
        }
        lutP[t] = make_float4(p00, p01, p10, p11);
        lutQ[t] = make_float4(q00, q01, q10, q11);
    }
    __syncthreads();

    const unsigned bits = smBits[t];   // thread t now owns segment t
    float4 P = lutP[bits & 15];
    float4 Q = lutQ[bits & 15];
#pragma unroll
    for (int c = 1; c < 8; c++) {
        unsigned m = (bits >> (4 * c)) & 15u;
        float4 M = lutP[m];
        float n00 = fmaxf(M.x * P.x, M.y * P.z), n01 = fmaxf(M.x * P.y, M.y * P.w);
        float n10 = fmaxf(M.z * P.x, M.w * P.z), n11 = fmaxf(M.z * P.y, M.w * P.w);
        P = make_float4(n00, n01, n10, n11);
        float4 N = lutQ[m];
        float m00 = fmaxf(Q.x * N.x, Q.y * N.z), m01 = fmaxf(Q.x * N.y, Q.y * N.w);
        float m10 = fmaxf(Q.z * N.x, Q.w * N.z), m11 = fmaxf(Q.z * N.y, Q.w * N.w);
        Q = make_float4(m00, m01, m10, m11);
    }

    const size_t idx = (size_t)b * NSEG + t;       // coalesced stores
    reinterpret_cast<float4*>(g_P)[idx] = P;
    reinterpret_cast<float4*>(g_Q)[idx] = Q;
    g_bits[idx] = bits;
}

// ---------------------------------------------------------------------------
// Phase 2: per-row sequential scans over segments (64-thread blocks for
// better SM spread).
// ---------------------------------------------------------------------------
__global__ void __launch_bounds__(64)
phase2()
{
    const int tid = blockIdx.x * 64 + threadIdx.x;
    if (tid < BATCH) {
        const int b = tid;
        const float4* P = reinterpret_cast<const float4*>(g_P) + (size_t)b * NSEG;
        float2*       F = reinterpret_cast<float2*>(g_F) + (size_t)b * NSEG;
        float f0 = 1.f, f1 = 1.f;
#pragma unroll 4
        for (int s = 0; s < NSEG; s++) {
            F[s] = make_float2(f0, f1);
            float4 p = P[s];
            float n0 = fmaxf(p.x * f0, p.y * f1);
            float n1 = fmaxf(p.z * f0, p.w * f1);
            f0 = n0; f1 = n1;
        }
    } else if (tid < 2 * BATCH) {
        const int b = tid - BATCH;
        const float4* Q = reinterpret_cast<const float4*>(g_Q) + (size_t)b * NSEG;
        float2*       G = reinterpret_cast<float2*>(g_G) + (size_t)b * NSEG;
        float g0 = 1.f, g1 = 1.f;
#pragma unroll 4
        for (int s = NSEG - 1; s >= 0; s--) {
            G[s] = make_float2(g0, g1);
            float4 q = Q[s];
            float n0 = fmaxf(q.x * g0, q.y * g1);
            float n1 = fmaxf(q.z * g0, q.w * g1);
            g0 = n0; g1 = n1;
        }
    }
}

// ---------------------------------------------------------------------------
// Phase 3: one block per row. Beliefs computed into swizzled smem tile,
// then cooperatively stored fully coalesced.
// ---------------------------------------------------------------------------
__global__ void __launch_bounds__(128)
phase3(const float* __restrict__ jp, const float* __restrict__ bp,
       float* __restrict__ out)
{
    const int s = threadIdx.x, b = blockIdx.x;
    __shared__ float smo[2 * LCH];                 // 32 KB output stage
    float4* sm4 = reinterpret_cast<float4*>(smo);

    const Pots pt = make_pots(jp, bp);

    const size_t idx = (size_t)b * NSEG + s;       // coalesced loads
    const unsigned bits = g_bits[idx];
    const float2 F2 = reinterpret_cast<const float2*>(g_F)[idx];
    const float2 G2 = reinterpret_cast<const float2*>(g_G)[idx];

    // Backward messages within segment (registers)
    float bk0[SEG], bk1[SEG];
    bk0[SEG - 1] = G2.x;  bk1[SEG - 1] = G2.y;
#pragma unroll
    for (int i = SEG - 2; i >= 0; i--) {
        int   o  = (bits >> (i + 1)) & 1;
        float f0 = o ? pt.pB0 : pt.pA0;
        float f1 = o ? pt.pB1 : pt.pA1;
        float x0 = f0 * bk0[i + 1];
        float x1 = f1 * bk1[i + 1];
        bk0[i] = fmaxf(x0 * pt.pd, x1 * pt.po);
        bk1[i] = fmaxf(x0 * pt.po, x1 * pt.pd);
    }

    // Forward sweep; beliefs into smem with float4-group swizzle (^ s&7)
    float f0 = F2.x, f1 = F2.y;
    const int xr = s & 7;
#pragma unroll
    for (int g = 0; g < 8; g++) {
        float v0[4], v1[4];
#pragma unroll
        for (int u = 0; u < 4; u++) {
            int   i  = g * 4 + u;
            int   o  = (bits >> i) & 1;
            float p0 = o ? pt.pB0 : pt.pA0;
            float p1 = o ? pt.pB1 : pt.pA1;
            float x0 = p0 * f0, x1 = p1 * f1;
            v0[u] = x0 * bk0[i];
            v1[u] = x1 * bk1[i];
            f0 = fmaxf(x0 * pt.pd, x1 * pt.po);
            f1 = fmaxf(x0 * pt.po, x1 * pt.pd);
        }
        sm4[(s * 8 + g) ^ xr]        = make_float4(v0[0], v0[1], v0[2], v0[3]);
        sm4[(1024 + s * 8 + g) ^ xr] = make_float4(v1[0], v1[1], v1[2], v1[3]);
    }
    __syncthreads();

    // Coalesced cooperative store of the whole row: out[b][k][t]
    float4* out4 = reinterpret_cast<float4*>(out) + (size_t)b * 2048;
#pragma unroll
    for (int r = 0; r < 16; r++) {
        int w4 = r * 128 + s;                       // float4 index within row
        int x  = (w4 >> 3) & 7;                     // matches writer's (s&7)
        out4[w4] = sm4[w4 ^ x];
    }
}

// ---------------------------------------------------------------------------
extern "C" void kernel_launch(void* const* d_in, const int* in_sizes, int n_in,
                              void* d_out, int out_size)
{
    const float* jp  = nullptr;
    const float* bp  = nullptr;
    const int*   obs = nullptr;
    for (int i = 0; i < n_in; i++) {
        if (in_sizes[i] == 1)      jp  = (const float*)d_in[i];
        else if (in_sizes[i] == 2) bp  = (const float*)d_in[i];
        else                       obs = (const int*)d_in[i];
    }
    float* out = (float*)d_out;

    phase1<<<BATCH, NSEG>>>(jp, bp, obs);
    phase2<<<(2 * BATCH + 63) / 64, 64>>>();
    phase3<<<BATCH, NSEG>>>(jp, bp, out);
}

// round 3
// speedup vs baseline: 2.0182x; 1.4870x over previous
#include <cuda_runtime.h>
#include <cstddef>

#define LCH   4096
#define BATCH 4096
#define SEG   32
#define NSEG  128

struct Pots { float pd, po, pA0, pA1, pB0, pB1; };

__device__ __forceinline__ Pots make_pots(const float* jp, const float* bp) {
    Pots P;
    float j = jp[0], b0 = bp[0], b1 = bp[1];
    P.pd  = expf( 0.25f * j);
    P.po  = expf(-0.25f * j);
    P.pA0 = expf(-0.5f * b0);  P.pA1 = expf(0.5f * b0);
    P.pB0 = expf(-0.5f * b1);  P.pB1 = expf(0.5f * b1);
    return P;
}

// (max,*) 2x2 matrix product: C = A x B.  layout x=m00 y=m01 z=m10 w=m11
__device__ __forceinline__ float4 mm(float4 A, float4 B) {
    return make_float4(
        fmaxf(A.x * B.x, A.y * B.z), fmaxf(A.x * B.y, A.y * B.w),
        fmaxf(A.z * B.x, A.w * B.z), fmaxf(A.z * B.y, A.w * B.w));
}

__device__ __forceinline__ float4 shflup4(float4 v, int d) {
    v.x = __shfl_up_sync(0xffffffffu, v.x, d);
    v.y = __shfl_up_sync(0xffffffffu, v.y, d);
    v.z = __shfl_up_sync(0xffffffffu, v.z, d);
    v.w = __shfl_up_sync(0xffffffffu, v.w, d);
    return v;
}
__device__ __forceinline__ float4 shfldn4(float4 v, int d) {
    v.x = __shfl_down_sync(0xffffffffu, v.x, d);
    v.y = __shfl_down_sync(0xffffffffu, v.y, d);
    v.z = __shfl_down_sync(0xffffffffu, v.z, d);
    v.w = __shfl_down_sync(0xffffffffu, v.w, d);
    return v;
}

// ---------------------------------------------------------------------------
// One block per row: segment transfer matrices -> block-level (max,*) matrix
// scan -> per-segment belief reconstruction -> coalesced store.
// ---------------------------------------------------------------------------
__global__ void __launch_bounds__(128)
fused(const float* __restrict__ jp, const float* __restrict__ bp,
      const int* __restrict__ obs, float* __restrict__ out)
{
    const int t = threadIdx.x, b = blockIdx.x;
    const int lane = t & 31, warp = t >> 5;

    __shared__ unsigned char smNib[1024];   // nibble per 4 obs positions
    __shared__ float4 lutP[16], lutQ[16];
    __shared__ float4 wTotP[4], wTotQ[4];
    __shared__ float  smo[2 * LCH];         // 32 KB output stage
    float4* sm4 = reinterpret_cast<float4*>(smo);

    const Pots pt = make_pots(jp, bp);

    // ---- obs -> nibbles (coalesced int4 loads, 8 per thread) ----
    const int4* row4 = reinterpret_cast<const int4*>(obs + (size_t)b * LCH);
#pragma unroll
    for (int q = 0; q < 8; q++) {
        int  eq = q * 128 + t;
        int4 v  = row4[eq];
        unsigned nib = (v.x & 1) | ((v.y & 1) << 1) | ((v.z & 1) << 2) | ((v.w & 1) << 3);
        smNib[eq] = (unsigned char)nib;
    }

    // ---- 4-bit LUTs of 4-step transfer matrices ----
    if (t < 16) {
        float p00 = 1.f, p01 = 0.f, p10 = 0.f, p11 = 1.f;
        float q00 = 1.f, q01 = 0.f, q10 = 0.f, q11 = 1.f;
#pragma unroll
        for (int i = 0; i < 4; i++) {
            int   o  = (t >> i) & 1;
            float f0 = o ? pt.pB0 : pt.pA0;
            float f1 = o ? pt.pB1 : pt.pA1;
            // P <- A_i (x) P   (applied-after, left compose)
            float x0 = f0 * p00, x1 = f1 * p10, y0 = f0 * p01, y1 = f1 * p11;
            p00 = fmaxf(x0 * pt.pd, x1 * pt.po); p10 = fmaxf(x0 * pt.po, x1 * pt.pd);
            p01 = fmaxf(y0 * pt.pd, y1 * pt.po); p11 = fmaxf(y0 * pt.po, y1 * pt.pd);
            // Q <- Q x A_i    (in-position-order right multiply)
            float a = f0 * fmaxf(q00 * pt.pd, q01 * pt.po);
            float c = f1 * fmaxf(q00 * pt.po, q01 * pt.pd);
            float d = f0 * fmaxf(q10 * pt.pd, q11 * pt.po);
            float e = f1 * fmaxf(q10 * pt.po, q11 * pt.pd);
            q00 = a; q01 = c; q10 = d; q11 = e;
        }
        lutP[t] = make_float4(p00, p01, p10, p11);
        lutQ[t] = make_float4(q00, q01, q10, q11);
    }
    __syncthreads();

    // ---- assemble 32-bit mask for segment t from 8 nibbles ----
    uint2 nb = reinterpret_cast<const uint2*>(smNib)[t];
    unsigned lo   = nb.x | (nb.x >> 4);
    unsigned lo16 = (lo & 0xFFu) | ((lo >> 8) & 0xFF00u);
    unsigned hi   = nb.y | (nb.y >> 4);
    unsigned hi16 = (hi & 0xFFu) | ((hi >> 8) & 0xFF00u);
    const unsigned bits = lo16 | (hi16 << 16);

    // ---- segment transfer matrices via LUT chains ----
    float4 P = lutP[bits & 15];
    float4 Q = lutQ[bits & 15];
#pragma unroll
    for (int c = 1; c < 8; c++) {
        unsigned m = (bits >> (4 * c)) & 15u;
        P = mm(lutP[m], P);     // later chunk composes on the left
        Q = mm(Q, lutQ[m]);     // position order, left to right
    }

    // ---- block-level scan: forward prefix of P, backward suffix of Q ----
    float4 sp = P;
#pragma unroll
    for (int d = 1; d < 32; d <<= 1) {
        float4 o = shflup4(sp, d);
        if (lane >= d) sp = mm(sp, o);
    }
    if (lane == 31) wTotP[warp] = sp;

    float4 sq = Q;
#pragma unroll
    for (int d = 1; d < 32; d <<= 1) {
        float4 o = shfldn4(sq, d);
        if (lane + d < 32) sq = mm(sq, o);
    }
    if (lane == 0) wTotQ[warp] = sq;
    __syncthreads();

    float4 prefP = make_float4(1.f, 0.f, 0.f, 1.f);
#pragma unroll
    for (int k = 2; k >= 0; k--)
        if (warp > k) prefP = mm(prefP, wTotP[k]);

    float4 sufQ = make_float4(1.f, 0.f, 0.f, 1.f);
#pragma unroll
    for (int k = 1; k < 4; k++)
        if (warp < k) sufQ = mm(sufQ, wTotQ[k]);

    float4 exP = shflup4(sp, 1);
    if (lane == 0) exP = make_float4(1.f, 0.f, 0.f, 1.f);
    exP = mm(exP, prefP);
    float f0 = fmaxf(exP.x, exP.y), f1 = fmaxf(exP.z, exP.w);  // fwd msg at seg start

    float4 exQ = shfldn4(sq, 1);
    if (lane == 31) exQ = make_float4(1.f, 0.f, 0.f, 1.f);
    exQ = mm(exQ, sufQ);
    float g0 = fmaxf(exQ.x, exQ.y), g1 = fmaxf(exQ.z, exQ.w);  // bwd msg at seg end

    // ---- forward sweep: x = phi * f into swizzled tile ----
    const int xr = t & 7;
#pragma unroll
    for (int gg = 0; gg < 8; gg++) {
        float v0[4], v1[4];
#pragma unroll
        for (int u = 0; u < 4; u++) {
            int   i  = gg * 4 + u;
            int   o  = (bits >> i) & 1;
            float p0 = o ? pt.pB0 : pt.pA0;
            float p1 = o ? pt.pB1 : pt.pA1;
            float x0 = p0 * f0, x1 = p1 * f1;
            v0[u] = x0;  v1[u] = x1;
            f0 = fmaxf(x0 * pt.pd, x1 * pt.po);
            f1 = fmaxf(x0 * pt.po, x1 * pt.pd);
        }
        sm4[(t * 8 + gg) ^ xr]        = make_float4(v0[0], v0[1], v0[2], v0[3]);
        sm4[(1024 + t * 8 + gg) ^ xr] = make_float4(v1[0], v1[1], v1[2], v1[3]);
    }

    // ---- backward sweep: in-place multiply by backward message ----
    float bk0 = g0, bk1 = g1;
#pragma unroll
    for (int gg = 7; gg >= 0; gg--) {
        float a0[4], a1[4];
        *reinterpret_cast<float4*>(a0) = sm4[(t * 8 + gg) ^ xr];
        *reinterpret_cast<float4*>(a1) = sm4[(1024 + t * 8 + gg) ^ xr];
        float r0[4], r1[4];
#pragma unroll
        for (int u = 3; u >= 0; u--) {
            int i = gg * 4 + u;
            r0[u] = a0[u] * bk0;
            r1[u] = a1[u] * bk1;
            // bk_{i-1} = A_i x bk_i   (A[k][l] = psi[k,l]*phi_i[l])
            int   o  = (bits >> i) & 1;
            float p0 = o ? pt.pB0 : pt.pA0;
            float p1 = o ? pt.pB1 : pt.pA1;
            float y0 = p0 * bk0, y1 = p1 * bk1;
            bk0 = fmaxf(y0 * pt.pd, y1 * pt.po);
            bk1 = fmaxf(y0 * pt.po, y1 * pt.pd);
        }
        sm4[(t * 8 + gg) ^ xr]        = *reinterpret_cast<float4*>(r0);
        sm4[(1024 + t * 8 + gg) ^ xr] = *reinterpret_cast<float4*>(r1);
    }
    __syncthreads();

    // ---- cooperative fully-coalesced store of the row: out[b][k][t] ----
    float4* out4 = reinterpret_cast<float4*>(out) + (size_t)b * 2048;
#pragma unroll
    for (int r = 0; r < 16; r++) {
        int w4 = r * 128 + t;
        int x  = (w4 >> 3) & 7;
        out4[w4] = sm4[w4 ^ x];
    }
}

// ---------------------------------------------------------------------------
extern "C" void kernel_launch(void* const* d_in, const int* in_sizes, int n_in,
                              void* d_out, int out_size)
{
    const float* jp  = nullptr;
    const float* bp  = nullptr;
    const int*   obs = nullptr;
    for (int i = 0; i < n_in; i++) {
        if (in_sizes[i] == 1)      jp  = (const float*)d_in[i];
        else if (in_sizes[i] == 2) bp  = (const float*)d_in[i];
        else                       obs = (const int*)d_in[i];
    }
    float* out = (float*)d_out;

    fused<<<BATCH, 128>>>(jp, bp, obs, out);
}